// round 12
// baseline (speedup 1.0000x reference)
#include <cuda_runtime.h>
#include <cuda_bf16.h>
#include <cstdint>
#include <cstddef>

// ============================================================================
// GAT 2-layer, N=50000, E=800000 (+self loops), fp32 in/out.
// R7 structure (best: 448.6us) + ldmatrix GEMM mainloop.
// GEMMs: mma.sync.m16n8k16 bf16 hi/lo split (3-product, K'=3K), fp32 acc.
// ============================================================================
#define NN    50000
#define EMAX  800000
#define ETOT  (EMAX + NN)
#define HC0   256
#define C1    128

// ---------------- static device scratch ----------------
__device__ int g_deg[NN];
__device__ int g_offs[NN + 1];
__device__ int g_cur[NN];
__device__ int g_csr[ETOT];

__device__ float g_h0[(size_t)NN * HC0];   // x @ W0 (fp32)
__device__ float g_h1[(size_t)NN * C1];    // g @ W1 (fp32)

__device__ __align__(16) __nv_bfloat16 g_xhi[(size_t)NN * 128];
__device__ __align__(16) __nv_bfloat16 g_xlo[(size_t)NN * 128];
__device__ __align__(16) __nv_bfloat16 g_ghi[(size_t)NN * HC0];
__device__ __align__(16) __nv_bfloat16 g_glo[(size_t)NN * HC0];
__device__ __align__(16) __nv_bfloat16 g_w0thi[256 * 128];  // W0^T [N][K]
__device__ __align__(16) __nv_bfloat16 g_w0tlo[256 * 128];
__device__ __align__(16) __nv_bfloat16 g_w1thi[128 * 256];  // W1^T [N][K]
__device__ __align__(16) __nv_bfloat16 g_w1tlo[128 * 256];

__device__ float2 g_ss0[NN];
__device__ float2 g_sd0[NN];
__device__ float  g_ss1[NN];
__device__ float  g_sd1[NN];

__device__ float2 g_alpha0[ETOT];
__device__ float  g_alpha1[ETOT];

// ============================================================================
// helpers
// ============================================================================
__device__ __forceinline__ uint32_t smem_u32(const void* p) {
    uint32_t a;
    asm("{ .reg .u64 t; cvta.to.shared.u64 t, %1; cvt.u32.u64 %0, t; }"
        : "=r"(a) : "l"(p));
    return a;
}
__device__ __forceinline__ void cp_async16(uint32_t dst, const void* src) {
    asm volatile("cp.async.cg.shared.global [%0], [%1], 16;"
                 :: "r"(dst), "l"(src) : "memory");
}
__device__ __forceinline__ void cp_commit() {
    asm volatile("cp.async.commit_group;" ::: "memory");
}
template <int N>
__device__ __forceinline__ void cp_wait() {
    asm volatile("cp.async.wait_group %0;" :: "n"(N) : "memory");
}
__device__ __forceinline__ void mma16816(float& c0, float& c1, float& c2, float& c3,
                                         uint32_t a0, uint32_t a1, uint32_t a2,
                                         uint32_t a3, uint32_t b0, uint32_t b1) {
    asm volatile(
        "mma.sync.aligned.m16n8k16.row.col.f32.bf16.bf16.f32 "
        "{%0,%1,%2,%3}, {%4,%5,%6,%7}, {%8,%9}, {%0,%1,%2,%3};"
        : "+f"(c0), "+f"(c1), "+f"(c2), "+f"(c3)
        : "r"(a0), "r"(a1), "r"(a2), "r"(a3), "r"(b0), "r"(b1));
}
__device__ __forceinline__ void ldsm_x4(uint32_t& r0, uint32_t& r1,
                                        uint32_t& r2, uint32_t& r3, uint32_t addr) {
    asm volatile("ldmatrix.sync.aligned.m8n8.x4.shared.b16 {%0,%1,%2,%3}, [%4];"
                 : "=r"(r0), "=r"(r1), "=r"(r2), "=r"(r3) : "r"(addr));
}

// ============================================================================
// CSR build
// ============================================================================
__global__ void init_deg_kernel() {
    int i = blockIdx.x * blockDim.x + threadIdx.x;
    if (i < NN) g_deg[i] = 1;
}
__global__ void count_kernel(const int* __restrict__ edst, int E) {
    int i = blockIdx.x * blockDim.x + threadIdx.x;
    if (i < E) atomicAdd(&g_deg[edst[i]], 1);
}
__global__ void scan_kernel() {
    __shared__ int sums[1024];
    int tid = threadIdx.x;
    const int per = (NN + 1023) / 1024;
    int start = tid * per;
    int end = min(start + per, NN);
    int s = 0;
    for (int i = start; i < end; i++) s += g_deg[i];
    sums[tid] = s;
    __syncthreads();
    for (int off = 1; off < 1024; off <<= 1) {
        int v = (tid >= off) ? sums[tid - off] : 0;
        __syncthreads();
        sums[tid] += v;
        __syncthreads();
    }
    int run = (tid == 0) ? 0 : sums[tid - 1];
    for (int i = start; i < end; i++) {
        g_offs[i] = run;
        g_cur[i]  = run;
        run += g_deg[i];
    }
    if (tid == 1023) g_offs[NN] = sums[1023];
}
__global__ void scatter_kernel(const int* __restrict__ esrc,
                               const int* __restrict__ edst, int E) {
    int i = blockIdx.x * blockDim.x + threadIdx.x;
    int tot = E + NN;
    if (i >= tot) return;
    int s, d;
    if (i < E) { s = esrc[i]; d = edst[i]; } else { s = i - E; d = s; }
    int pos = atomicAdd(&g_cur[d], 1);
    g_csr[pos] = s;
}

// ============================================================================
// bf16 hi/lo split conversions
// ============================================================================
__global__ void split_x_kernel(const float* __restrict__ x) {
    int i = blockIdx.x * blockDim.x + threadIdx.x;
    if (i >= NN * 128) return;
    float v = x[i];
    __nv_bfloat16 h = __float2bfloat16(v);
    g_xhi[i] = h;
    g_xlo[i] = __float2bfloat16(v - __bfloat162float(h));
}
__global__ void splitT_kernel(const float* __restrict__ W,
                              __nv_bfloat16* __restrict__ hi,
                              __nv_bfloat16* __restrict__ lo, int K, int N) {
    int i = blockIdx.x * blockDim.x + threadIdx.x;
    if (i >= K * N) return;
    int k = i / N, n = i % N;
    float v = W[i];
    __nv_bfloat16 h = __float2bfloat16(v);
    hi[(size_t)n * K + k] = h;
    lo[(size_t)n * K + k] = __float2bfloat16(v - __bfloat162float(h));
}

// ============================================================================
// bf16 split-GEMM via mma.sync + ldmatrix.
// Block 128x128, 256 thr (2x4 warps, warp tile 64x32), Kc=32, double-buffered.
// ============================================================================
#define KC 32
#define ROWW 20   // words per smem row (16 data + 4 pad); 80 B = 5*16 (aligned)

__global__ void __launch_bounds__(256)
gemm_bf16_kernel(const __nv_bfloat16* __restrict__ Ahi,
                 const __nv_bfloat16* __restrict__ Alo,
                 const __nv_bfloat16* __restrict__ Bhi,
                 const __nv_bfloat16* __restrict__ Blo,
                 float* __restrict__ C, int K, int ldC) {
    __shared__ uint32_t As[2][128][ROWW];
    __shared__ uint32_t Bs[2][128][ROWW];

    const int tid  = threadIdx.x;
    const int wid  = tid >> 5;
    const int lane = tid & 31;
    const int g    = lane >> 2;
    const int tg   = lane & 3;
    const int wm   = wid & 1;
    const int wn   = wid >> 1;

    // ldmatrix lane->address decomposition
    const int mat   = lane >> 3;         // matrix index 0..3
    const int mrow  = lane & 7;          // row within matrix
    const int aRow  = (mat & 1) * 8 + mrow;     // A: mat0/2 = m+0, mat1/3 = m+8
    const int aKw   = (mat >> 1) * 4;           //    mat0/1 = k lo, mat2/3 = k hi
    const int bRow  = (mat >> 1) * 8 + mrow;    // B: mat0/1 = n+0, mat2/3 = n+8
    const int bKw   = (mat & 1) * 4;            //    mat0/2 = k lo, mat1/3 = k hi

    const int m0 = blockIdx.x * 128;
    const int n0 = blockIdx.y * 128;
    const int nChunks = (3 * K) / KC;

    const int r0 = tid >> 2;
    const int c0 = tid & 3;
    const int r1 = r0 + 64;

    float acc[4][4][4];
#pragma unroll
    for (int i = 0; i < 4; i++)
#pragma unroll
        for (int j = 0; j < 4; j++)
#pragma unroll
            for (int t = 0; t < 4; t++) acc[i][j][t] = 0.f;

    auto stage = [&](int ch, int buf) {
        int k0 = ch * KC;
        int seg = k0 / K;
        int kk = k0 - seg * K;
        const __nv_bfloat16* Asrc = (seg < 2) ? Ahi : Alo;
        const __nv_bfloat16* Bsrc = (seg == 1) ? Blo : Bhi;
        int ga0 = min(m0 + r0, NN - 1);
        int ga1 = min(m0 + r1, NN - 1);
        cp_async16(smem_u32(&As[buf][r0][c0 * 4]),
                   (const char*)(Asrc + (size_t)ga0 * K + kk) + c0 * 16);
        cp_async16(smem_u32(&As[buf][r1][c0 * 4]),
                   (const char*)(Asrc + (size_t)ga1 * K + kk) + c0 * 16);
        cp_async16(smem_u32(&Bs[buf][r0][c0 * 4]),
                   (const char*)(Bsrc + (size_t)(n0 + r0) * K + kk) + c0 * 16);
        cp_async16(smem_u32(&Bs[buf][r1][c0 * 4]),
                   (const char*)(Bsrc + (size_t)(n0 + r1) * K + kk) + c0 * 16);
        cp_commit();
    };

    stage(0, 0);

    for (int ch = 0; ch < nChunks; ch++) {
        int buf = ch & 1;
        if (ch + 1 < nChunks) {
            stage(ch + 1, buf ^ 1);
            cp_wait<1>();
        } else {
            cp_wait<0>();
        }
        __syncthreads();

#pragma unroll
        for (int k16 = 0; k16 < 2; k16++) {
            const int kw = k16 * 8;
            uint32_t a[4][4], b[4][2];
#pragma unroll
            for (int mi = 0; mi < 4; mi++) {
                uint32_t addr = smem_u32(&As[buf][wm * 64 + mi * 16 + aRow][kw + aKw]);
                ldsm_x4(a[mi][0], a[mi][1], a[mi][2], a[mi][3], addr);
            }
#pragma unroll
            for (int p = 0; p < 2; p++) {
                uint32_t addr = smem_u32(&Bs[buf][wn * 32 + p * 16 + bRow][kw + bKw]);
                ldsm_x4(b[2 * p][0], b[2 * p][1], b[2 * p + 1][0], b[2 * p + 1][1], addr);
            }
#pragma unroll
            for (int mi = 0; mi < 4; mi++)
#pragma unroll
                for (int ni = 0; ni < 4; ni++)
                    mma16816(acc[mi][ni][0], acc[mi][ni][1],
                             acc[mi][ni][2], acc[mi][ni][3],
                             a[mi][0], a[mi][1], a[mi][2], a[mi][3],
                             b[ni][0], b[ni][1]);
        }
        __syncthreads();
    }

#pragma unroll
    for (int mi = 0; mi < 4; mi++) {
        int row0 = m0 + wm * 64 + mi * 16 + g;
        int row1 = row0 + 8;
#pragma unroll
        for (int ni = 0; ni < 4; ni++) {
            int col = n0 + wn * 32 + ni * 8 + tg * 2;
            if (row0 < NN)
                *(float2*)&C[(size_t)row0 * ldC + col] =
                    make_float2(acc[mi][ni][0], acc[mi][ni][1]);
            if (row1 < NN)
                *(float2*)&C[(size_t)row1 * ldC + col] =
                    make_float2(acc[mi][ni][2], acc[mi][ni][3]);
        }
    }
}

// ============================================================================
// Per-node attention scores (warp per node)
// ============================================================================
__global__ void sfuse0_kernel(const float* __restrict__ a_src,
                              const float* __restrict__ a_dst) {
    int w = (blockIdx.x * blockDim.x + threadIdx.x) >> 5;
    int lane = threadIdx.x & 31;
    if (w >= NN) return;
    const float* hrow = &g_h0[(size_t)w * HC0];
    float ss0 = 0.f, sd0 = 0.f, ss1 = 0.f, sd1 = 0.f;
#pragma unroll
    for (int k = lane; k < 128; k += 32) {
        float v0 = hrow[k];
        float v1 = hrow[128 + k];
        ss0 = fmaf(v0, a_src[k], ss0);
        sd0 = fmaf(v0, a_dst[k], sd0);
        ss1 = fmaf(v1, a_src[128 + k], ss1);
        sd1 = fmaf(v1, a_dst[128 + k], sd1);
    }
#pragma unroll
    for (int o = 16; o; o >>= 1) {
        ss0 += __shfl_xor_sync(0xffffffffu, ss0, o);
        sd0 += __shfl_xor_sync(0xffffffffu, sd0, o);
        ss1 += __shfl_xor_sync(0xffffffffu, ss1, o);
        sd1 += __shfl_xor_sync(0xffffffffu, sd1, o);
    }
    if (lane == 0) {
        g_ss0[w] = make_float2(ss0, ss1);
        g_sd0[w] = make_float2(sd0, sd1);
    }
}
__global__ void sfuse1_kernel(const float* __restrict__ a_src,
                              const float* __restrict__ a_dst) {
    int w = (blockIdx.x * blockDim.x + threadIdx.x) >> 5;
    int lane = threadIdx.x & 31;
    if (w >= NN) return;
    const float* hrow = &g_h1[(size_t)w * C1];
    float ss = 0.f, sd = 0.f;
#pragma unroll
    for (int k = lane; k < 128; k += 32) {
        float v = hrow[k];
        ss = fmaf(v, a_src[k], ss);
        sd = fmaf(v, a_dst[k], sd);
    }
#pragma unroll
    for (int o = 16; o; o >>= 1) {
        ss += __shfl_xor_sync(0xffffffffu, ss, o);
        sd += __shfl_xor_sync(0xffffffffu, sd, o);
    }
    if (lane == 0) { g_ss1[w] = ss; g_sd1[w] = sd; }
}

// ============================================================================
// Scatter-softmax (warp per destination node)
// ============================================================================
__global__ void attn0_kernel() {
    int v = (blockIdx.x * blockDim.x + threadIdx.x) >> 5;
    int lane = threadIdx.x & 31;
    if (v >= NN) return;
    int off = g_offs[v], end = g_offs[v + 1];
    float2 sd = g_sd0[v];
    float m0 = -1e30f, m1 = -1e30f;
    for (int j = off + lane; j < end; j += 32) {
        int u = g_csr[j];
        float2 ss = g_ss0[u];
        float e0 = ss.x + sd.x;  e0 = e0 > 0.f ? e0 : 0.2f * e0;
        float e1 = ss.y + sd.y;  e1 = e1 > 0.f ? e1 : 0.2f * e1;
        g_alpha0[j] = make_float2(e0, e1);
        m0 = fmaxf(m0, e0); m1 = fmaxf(m1, e1);
    }
#pragma unroll
    for (int o = 16; o; o >>= 1) {
        m0 = fmaxf(m0, __shfl_xor_sync(0xffffffffu, m0, o));
        m1 = fmaxf(m1, __shfl_xor_sync(0xffffffffu, m1, o));
    }
    float d0 = 0.f, d1 = 0.f;
    for (int j = off + lane; j < end; j += 32) {
        float2 e = g_alpha0[j];
        float w0 = __expf(e.x - m0), w1 = __expf(e.y - m1);
        g_alpha0[j] = make_float2(w0, w1);
        d0 += w0; d1 += w1;
    }
#pragma unroll
    for (int o = 16; o; o >>= 1) {
        d0 += __shfl_xor_sync(0xffffffffu, d0, o);
        d1 += __shfl_xor_sync(0xffffffffu, d1, o);
    }
    float i0 = 1.f / (d0 + 1e-16f), i1 = 1.f / (d1 + 1e-16f);
    for (int j = off + lane; j < end; j += 32) {
        float2 a = g_alpha0[j];
        g_alpha0[j] = make_float2(a.x * i0, a.y * i1);
    }
}
__global__ void attn1_kernel() {
    int v = (blockIdx.x * blockDim.x + threadIdx.x) >> 5;
    int lane = threadIdx.x & 31;
    if (v >= NN) return;
    int off = g_offs[v], end = g_offs[v + 1];
    float sd = g_sd1[v];
    float m = -1e30f;
    for (int j = off + lane; j < end; j += 32) {
        int u = g_csr[j];
        float e = g_ss1[u] + sd;  e = e > 0.f ? e : 0.2f * e;
        g_alpha1[j] = e;
        m = fmaxf(m, e);
    }
#pragma unroll
    for (int o = 16; o; o >>= 1) m = fmaxf(m, __shfl_xor_sync(0xffffffffu, m, o));
    float d = 0.f;
    for (int j = off + lane; j < end; j += 32) {
        float w = __expf(g_alpha1[j] - m);
        g_alpha1[j] = w;
        d += w;
    }
#pragma unroll
    for (int o = 16; o; o >>= 1) d += __shfl_xor_sync(0xffffffffu, d, o);
    float iv = 1.f / (d + 1e-16f);
    for (int j = off + lane; j < end; j += 32) g_alpha1[j] *= iv;
}

// ============================================================================
// Aggregation (block per dst node, thread per channel; no atomics).
// agg0 emits g directly as bf16 hi/lo (layer-1 GEMM A operand).
// ============================================================================
__global__ void __launch_bounds__(256) agg0_kernel(const float* __restrict__ b0) {
    int v = blockIdx.x;
    int tid = threadIdx.x;
    int head = tid >> 7;
    int off = g_offs[v], end = g_offs[v + 1];
    __shared__ int   su[32];
    __shared__ float sa[64];
    float acc = 0.f;
    for (int j0 = off; j0 < end; j0 += 32) {
        int cnt = min(32, end - j0);
        if (tid < cnt) su[tid] = g_csr[j0 + tid];
        if (tid >= 128 && tid < 128 + 2 * cnt)
            sa[tid - 128] = reinterpret_cast<const float*>(g_alpha0)[2 * j0 + (tid - 128)];
        __syncthreads();
        int j = 0;
        for (; j + 4 <= cnt; j += 4) {
            float x0 = g_h0[(size_t)su[j]     * HC0 + tid];
            float x1 = g_h0[(size_t)su[j + 1] * HC0 + tid];
            float x2 = g_h0[(size_t)su[j + 2] * HC0 + tid];
            float x3 = g_h0[(size_t)su[j + 3] * HC0 + tid];
            acc = fmaf(sa[2 * j + head],       x0, acc);
            acc = fmaf(sa[2 * (j + 1) + head], x1, acc);
            acc = fmaf(sa[2 * (j + 2) + head], x2, acc);
            acc = fmaf(sa[2 * (j + 3) + head], x3, acc);
        }
        for (; j < cnt; j++)
            acc = fmaf(sa[2 * j + head], g_h0[(size_t)su[j] * HC0 + tid], acc);
        __syncthreads();
    }
    float val = acc + b0[tid];
    val = val > 0.f ? val : expm1f(val);   // elu
    __nv_bfloat16 h = __float2bfloat16(val);
    size_t oidx = (size_t)v * HC0 + tid;
    g_ghi[oidx] = h;
    g_glo[oidx] = __float2bfloat16(val - __bfloat162float(h));
}

__global__ void __launch_bounds__(128)
agg1_kernel(const float* __restrict__ x, const float* __restrict__ b1,
            float* __restrict__ out) {
    int v = blockIdx.x;
    int tid = threadIdx.x;
    int off = g_offs[v], end = g_offs[v + 1];
    __shared__ int   su[32];
    __shared__ float sa[32];
    float acc = 0.f;
    for (int j0 = off; j0 < end; j0 += 32) {
        int cnt = min(32, end - j0);
        if (tid < cnt) su[tid] = g_csr[j0 + tid];
        if (tid >= 64 && tid < 64 + cnt) sa[tid - 64] = g_alpha1[j0 + (tid - 64)];
        __syncthreads();
        int j = 0;
        for (; j + 4 <= cnt; j += 4) {
            float x0 = g_h1[(size_t)su[j]     * C1 + tid];
            float x1 = g_h1[(size_t)su[j + 1] * C1 + tid];
            float x2 = g_h1[(size_t)su[j + 2] * C1 + tid];
            float x3 = g_h1[(size_t)su[j + 3] * C1 + tid];
            acc = fmaf(sa[j],     x0, acc);
            acc = fmaf(sa[j + 1], x1, acc);
            acc = fmaf(sa[j + 2], x2, acc);
            acc = fmaf(sa[j + 3], x3, acc);
        }
        for (; j < cnt; j++)
            acc = fmaf(sa[j], g_h1[(size_t)su[j] * C1 + tid], acc);
        __syncthreads();
    }
    out[(size_t)v * C1 + tid] = x[(size_t)v * C1 + tid] + acc + b1[tid];
}

// ============================================================================
// Launch (R7 order; gemm0 is launch #4 — profiled slot)
// ============================================================================
extern "C" void kernel_launch(void* const* d_in, const int* in_sizes, int n_in,
                              void* d_out, int out_size) {
    const float* x      = (const float*)d_in[0];
    const float* W0     = (const float*)d_in[1];
    const float* a_src0 = (const float*)d_in[2];
    const float* a_dst0 = (const float*)d_in[3];
    const float* b0     = (const float*)d_in[4];
    const float* W1     = (const float*)d_in[5];
    const float* a_src1 = (const float*)d_in[6];
    const float* a_dst1 = (const float*)d_in[7];
    const float* b1     = (const float*)d_in[8];
    const int*   eidx   = (const int*)d_in[9];
    float* out = (float*)d_out;

    int E = in_sizes[9] / 2;
    if (E > EMAX) E = EMAX;
    const int* esrc = eidx;
    const int* edst = eidx + E;

    float *h0p = nullptr, *h1p = nullptr;
    __nv_bfloat16 *xhi, *xlo, *ghi, *glo, *w0thi, *w0tlo, *w1thi, *w1tlo;
    cudaGetSymbolAddress((void**)&h0p,   g_h0);
    cudaGetSymbolAddress((void**)&h1p,   g_h1);
    cudaGetSymbolAddress((void**)&xhi,   g_xhi);
    cudaGetSymbolAddress((void**)&xlo,   g_xlo);
    cudaGetSymbolAddress((void**)&ghi,   g_ghi);
    cudaGetSymbolAddress((void**)&glo,   g_glo);
    cudaGetSymbolAddress((void**)&w0thi, g_w0thi);
    cudaGetSymbolAddress((void**)&w0tlo, g_w0tlo);
    cudaGetSymbolAddress((void**)&w1thi, g_w1thi);
    cudaGetSymbolAddress((void**)&w1tlo, g_w1tlo);

    const int T = 256;
    int nWarpBlocks = (NN * 32 + T - 1) / T;
    int mTiles = (NN + 127) / 128;   // 391

    // conversions + CSR build
    split_x_kernel<<<(NN * 128 + T - 1) / T, T>>>(x);
    splitT_kernel<<<(128 * 256 + T - 1) / T, T>>>(W0, w0thi, w0tlo, 128, 256);
    splitT_kernel<<<(256 * 128 + T - 1) / T, T>>>(W1, w1thi, w1tlo, 256, 128);
    // gemm0 here is launch #4 -> profiled by ncu -s/-c window
    gemm_bf16_kernel<<<dim3(mTiles, 2), 256>>>(xhi, xlo, w0thi, w0tlo,
                                               h0p, 128, HC0);
    init_deg_kernel<<<(NN + T - 1) / T, T>>>();
    count_kernel<<<(E + T - 1) / T, T>>>(edst, E);
    scan_kernel<<<1, 1024>>>();
    scatter_kernel<<<(E + NN + T - 1) / T, T>>>(esrc, edst, E);

    // Layer 0 (post-gemm)
    sfuse0_kernel<<<nWarpBlocks, T>>>(a_src0, a_dst0);
    attn0_kernel<<<nWarpBlocks, T>>>();
    agg0_kernel<<<NN, 256>>>(b0);

    // Layer 1
    gemm_bf16_kernel<<<dim3(mTiles, 1), 256>>>(ghi, glo, w1thi, w1tlo,
                                               h1p, 256, C1);
    sfuse1_kernel<<<nWarpBlocks, T>>>(a_src1, a_dst1);
    attn1_kernel<<<nWarpBlocks, T>>>();
    agg1_kernel<<<NN, 128>>>(x, b1, out);
}

// round 13
// speedup vs baseline: 1.5090x; 1.5090x over previous
#include <cuda_runtime.h>
#include <cuda_bf16.h>
#include <cstdint>
#include <cstddef>

// ============================================================================
// GAT 2-layer, N=50000, E=800000 (+self loops), fp32 in/out.
// Exact R7 structure (best: 448.6us) with deepened agg unroll (4->8).
// GEMMs: mma.sync.m16n8k16 bf16 hi/lo split (3-product, K'=3K), fp32 acc.
// ============================================================================
#define NN    50000
#define EMAX  800000
#define ETOT  (EMAX + NN)
#define HC0   256
#define C1    128

// ---------------- static device scratch ----------------
__device__ int g_deg[NN];
__device__ int g_offs[NN + 1];
__device__ int g_cur[NN];
__device__ int g_csr[ETOT];

__device__ float g_h0[(size_t)NN * HC0];   // x @ W0 (fp32)
__device__ float g_h1[(size_t)NN * C1];    // g @ W1 (fp32)

__device__ __align__(16) __nv_bfloat16 g_xhi[(size_t)NN * 128];
__device__ __align__(16) __nv_bfloat16 g_xlo[(size_t)NN * 128];
__device__ __align__(16) __nv_bfloat16 g_ghi[(size_t)NN * HC0];
__device__ __align__(16) __nv_bfloat16 g_glo[(size_t)NN * HC0];
__device__ __align__(16) __nv_bfloat16 g_w0thi[256 * 128];  // W0^T [N][K]
__device__ __align__(16) __nv_bfloat16 g_w0tlo[256 * 128];
__device__ __align__(16) __nv_bfloat16 g_w1thi[128 * 256];  // W1^T [N][K]
__device__ __align__(16) __nv_bfloat16 g_w1tlo[128 * 256];

__device__ float2 g_ss0[NN];
__device__ float2 g_sd0[NN];
__device__ float  g_ss1[NN];
__device__ float  g_sd1[NN];

__device__ float2 g_alpha0[ETOT];
__device__ float  g_alpha1[ETOT];

// ============================================================================
// helpers
// ============================================================================
__device__ __forceinline__ uint32_t smem_u32(const void* p) {
    uint32_t a;
    asm("{ .reg .u64 t; cvta.to.shared.u64 t, %1; cvt.u32.u64 %0, t; }"
        : "=r"(a) : "l"(p));
    return a;
}
__device__ __forceinline__ void cp_async16(uint32_t dst, const void* src) {
    asm volatile("cp.async.cg.shared.global [%0], [%1], 16;"
                 :: "r"(dst), "l"(src) : "memory");
}
__device__ __forceinline__ void cp_commit() {
    asm volatile("cp.async.commit_group;" ::: "memory");
}
template <int N>
__device__ __forceinline__ void cp_wait() {
    asm volatile("cp.async.wait_group %0;" :: "n"(N) : "memory");
}
__device__ __forceinline__ void mma16816(float& c0, float& c1, float& c2, float& c3,
                                         uint32_t a0, uint32_t a1, uint32_t a2,
                                         uint32_t a3, uint32_t b0, uint32_t b1) {
    asm volatile(
        "mma.sync.aligned.m16n8k16.row.col.f32.bf16.bf16.f32 "
        "{%0,%1,%2,%3}, {%4,%5,%6,%7}, {%8,%9}, {%0,%1,%2,%3};"
        : "+f"(c0), "+f"(c1), "+f"(c2), "+f"(c3)
        : "r"(a0), "r"(a1), "r"(a2), "r"(a3), "r"(b0), "r"(b1));
}

// ============================================================================
// CSR build
// ============================================================================
__global__ void init_deg_kernel() {
    int i = blockIdx.x * blockDim.x + threadIdx.x;
    if (i < NN) g_deg[i] = 1;
}
__global__ void count_kernel(const int* __restrict__ edst, int E) {
    int i = blockIdx.x * blockDim.x + threadIdx.x;
    if (i < E) atomicAdd(&g_deg[edst[i]], 1);
}
__global__ void scan_kernel() {
    __shared__ int sums[1024];
    int tid = threadIdx.x;
    const int per = (NN + 1023) / 1024;
    int start = tid * per;
    int end = min(start + per, NN);
    int s = 0;
    for (int i = start; i < end; i++) s += g_deg[i];
    sums[tid] = s;
    __syncthreads();
    for (int off = 1; off < 1024; off <<= 1) {
        int v = (tid >= off) ? sums[tid - off] : 0;
        __syncthreads();
        sums[tid] += v;
        __syncthreads();
    }
    int run = (tid == 0) ? 0 : sums[tid - 1];
    for (int i = start; i < end; i++) {
        g_offs[i] = run;
        g_cur[i]  = run;
        run += g_deg[i];
    }
    if (tid == 1023) g_offs[NN] = sums[1023];
}
__global__ void scatter_kernel(const int* __restrict__ esrc,
                               const int* __restrict__ edst, int E) {
    int i = blockIdx.x * blockDim.x + threadIdx.x;
    int tot = E + NN;
    if (i >= tot) return;
    int s, d;
    if (i < E) { s = esrc[i]; d = edst[i]; } else { s = i - E; d = s; }
    int pos = atomicAdd(&g_cur[d], 1);
    g_csr[pos] = s;
}

// ============================================================================
// bf16 hi/lo split conversions
// ============================================================================
__global__ void split_x_kernel(const float* __restrict__ x) {
    int i = blockIdx.x * blockDim.x + threadIdx.x;
    if (i >= NN * 128) return;
    float v = x[i];
    __nv_bfloat16 h = __float2bfloat16(v);
    g_xhi[i] = h;
    g_xlo[i] = __float2bfloat16(v - __bfloat162float(h));
}
__global__ void splitT_kernel(const float* __restrict__ W,
                              __nv_bfloat16* __restrict__ hi,
                              __nv_bfloat16* __restrict__ lo, int K, int N) {
    int i = blockIdx.x * blockDim.x + threadIdx.x;
    if (i >= K * N) return;
    int k = i / N, n = i % N;
    float v = W[i];
    __nv_bfloat16 h = __float2bfloat16(v);
    hi[(size_t)n * K + k] = h;
    lo[(size_t)n * K + k] = __float2bfloat16(v - __bfloat162float(h));
}

// ============================================================================
// bf16 split-GEMM via mma.sync (R7 scalar-LDS mainloop — measured 51.6us).
// Block 128x128, 256 thr (2x4 warps, warp tile 64x32), Kc=32, double-buffered.
// ============================================================================
#define KC 32
#define ROWW 20   // words per smem row (16 data + 4 pad)

__global__ void __launch_bounds__(256)
gemm_bf16_kernel(const __nv_bfloat16* __restrict__ Ahi,
                 const __nv_bfloat16* __restrict__ Alo,
                 const __nv_bfloat16* __restrict__ Bhi,
                 const __nv_bfloat16* __restrict__ Blo,
                 float* __restrict__ C, int K, int ldC) {
    __shared__ uint32_t As[2][128][ROWW];
    __shared__ uint32_t Bs[2][128][ROWW];

    const int tid  = threadIdx.x;
    const int wid  = tid >> 5;
    const int lane = tid & 31;
    const int g    = lane >> 2;
    const int tg   = lane & 3;
    const int wm   = wid & 1;
    const int wn   = wid >> 1;

    const int m0 = blockIdx.x * 128;
    const int n0 = blockIdx.y * 128;
    const int nChunks = (3 * K) / KC;

    const int r0 = tid >> 2;
    const int c0 = tid & 3;
    const int r1 = r0 + 64;

    float acc[4][4][4];
#pragma unroll
    for (int i = 0; i < 4; i++)
#pragma unroll
        for (int j = 0; j < 4; j++)
#pragma unroll
            for (int t = 0; t < 4; t++) acc[i][j][t] = 0.f;

    auto stage = [&](int ch, int buf) {
        int k0 = ch * KC;
        int seg = k0 / K;
        int kk = k0 - seg * K;
        const __nv_bfloat16* Asrc = (seg < 2) ? Ahi : Alo;
        const __nv_bfloat16* Bsrc = (seg == 1) ? Blo : Bhi;
        int ga0 = min(m0 + r0, NN - 1);
        int ga1 = min(m0 + r1, NN - 1);
        cp_async16(smem_u32(&As[buf][r0][c0 * 4]),
                   (const char*)(Asrc + (size_t)ga0 * K + kk) + c0 * 16);
        cp_async16(smem_u32(&As[buf][r1][c0 * 4]),
                   (const char*)(Asrc + (size_t)ga1 * K + kk) + c0 * 16);
        cp_async16(smem_u32(&Bs[buf][r0][c0 * 4]),
                   (const char*)(Bsrc + (size_t)(n0 + r0) * K + kk) + c0 * 16);
        cp_async16(smem_u32(&Bs[buf][r1][c0 * 4]),
                   (const char*)(Bsrc + (size_t)(n0 + r1) * K + kk) + c0 * 16);
        cp_commit();
    };

    stage(0, 0);

    for (int ch = 0; ch < nChunks; ch++) {
        int buf = ch & 1;
        if (ch + 1 < nChunks) {
            stage(ch + 1, buf ^ 1);
            cp_wait<1>();
        } else {
            cp_wait<0>();
        }
        __syncthreads();

#pragma unroll
        for (int k16 = 0; k16 < 2; k16++) {
            const int kw = k16 * 8;
            uint32_t a[4][4], b[4][2];
#pragma unroll
            for (int mi = 0; mi < 4; mi++) {
                int ra = wm * 64 + mi * 16;
                a[mi][0] = As[buf][ra + g][kw + tg];
                a[mi][1] = As[buf][ra + g + 8][kw + tg];
                a[mi][2] = As[buf][ra + g][kw + tg + 4];
                a[mi][3] = As[buf][ra + g + 8][kw + tg + 4];
            }
#pragma unroll
            for (int ni = 0; ni < 4; ni++) {
                int rb = wn * 32 + ni * 8;
                b[ni][0] = Bs[buf][rb + g][kw + tg];
                b[ni][1] = Bs[buf][rb + g][kw + tg + 4];
            }
#pragma unroll
            for (int mi = 0; mi < 4; mi++)
#pragma unroll
                for (int ni = 0; ni < 4; ni++)
                    mma16816(acc[mi][ni][0], acc[mi][ni][1],
                             acc[mi][ni][2], acc[mi][ni][3],
                             a[mi][0], a[mi][1], a[mi][2], a[mi][3],
                             b[ni][0], b[ni][1]);
        }
        __syncthreads();
    }

#pragma unroll
    for (int mi = 0; mi < 4; mi++) {
        int row0 = m0 + wm * 64 + mi * 16 + g;
        int row1 = row0 + 8;
#pragma unroll
        for (int ni = 0; ni < 4; ni++) {
            int col = n0 + wn * 32 + ni * 8 + tg * 2;
            if (row0 < NN)
                *(float2*)&C[(size_t)row0 * ldC + col] =
                    make_float2(acc[mi][ni][0], acc[mi][ni][1]);
            if (row1 < NN)
                *(float2*)&C[(size_t)row1 * ldC + col] =
                    make_float2(acc[mi][ni][2], acc[mi][ni][3]);
        }
    }
}

// ============================================================================
// Per-node attention scores (warp per node)
// ============================================================================
__global__ void sfuse0_kernel(const float* __restrict__ a_src,
                              const float* __restrict__ a_dst) {
    int w = (blockIdx.x * blockDim.x + threadIdx.x) >> 5;
    int lane = threadIdx.x & 31;
    if (w >= NN) return;
    const float* hrow = &g_h0[(size_t)w * HC0];
    float ss0 = 0.f, sd0 = 0.f, ss1 = 0.f, sd1 = 0.f;
#pragma unroll
    for (int k = lane; k < 128; k += 32) {
        float v0 = hrow[k];
        float v1 = hrow[128 + k];
        ss0 = fmaf(v0, a_src[k], ss0);
        sd0 = fmaf(v0, a_dst[k], sd0);
        ss1 = fmaf(v1, a_src[128 + k], ss1);
        sd1 = fmaf(v1, a_dst[128 + k], sd1);
    }
#pragma unroll
    for (int o = 16; o; o >>= 1) {
        ss0 += __shfl_xor_sync(0xffffffffu, ss0, o);
        sd0 += __shfl_xor_sync(0xffffffffu, sd0, o);
        ss1 += __shfl_xor_sync(0xffffffffu, ss1, o);
        sd1 += __shfl_xor_sync(0xffffffffu, sd1, o);
    }
    if (lane == 0) {
        g_ss0[w] = make_float2(ss0, ss1);
        g_sd0[w] = make_float2(sd0, sd1);
    }
}
__global__ void sfuse1_kernel(const float* __restrict__ a_src,
                              const float* __restrict__ a_dst) {
    int w = (blockIdx.x * blockDim.x + threadIdx.x) >> 5;
    int lane = threadIdx.x & 31;
    if (w >= NN) return;
    const float* hrow = &g_h1[(size_t)w * C1];
    float ss = 0.f, sd = 0.f;
#pragma unroll
    for (int k = lane; k < 128; k += 32) {
        float v = hrow[k];
        ss = fmaf(v, a_src[k], ss);
        sd = fmaf(v, a_dst[k], sd);
    }
#pragma unroll
    for (int o = 16; o; o >>= 1) {
        ss += __shfl_xor_sync(0xffffffffu, ss, o);
        sd += __shfl_xor_sync(0xffffffffu, sd, o);
    }
    if (lane == 0) { g_ss1[w] = ss; g_sd1[w] = sd; }
}

// ============================================================================
// Scatter-softmax (warp per destination node)
// ============================================================================
__global__ void attn0_kernel() {
    int v = (blockIdx.x * blockDim.x + threadIdx.x) >> 5;
    int lane = threadIdx.x & 31;
    if (v >= NN) return;
    int off = g_offs[v], end = g_offs[v + 1];
    float2 sd = g_sd0[v];
    float m0 = -1e30f, m1 = -1e30f;
    for (int j = off + lane; j < end; j += 32) {
        int u = g_csr[j];
        float2 ss = g_ss0[u];
        float e0 = ss.x + sd.x;  e0 = e0 > 0.f ? e0 : 0.2f * e0;
        float e1 = ss.y + sd.y;  e1 = e1 > 0.f ? e1 : 0.2f * e1;
        g_alpha0[j] = make_float2(e0, e1);
        m0 = fmaxf(m0, e0); m1 = fmaxf(m1, e1);
    }
#pragma unroll
    for (int o = 16; o; o >>= 1) {
        m0 = fmaxf(m0, __shfl_xor_sync(0xffffffffu, m0, o));
        m1 = fmaxf(m1, __shfl_xor_sync(0xffffffffu, m1, o));
    }
    float d0 = 0.f, d1 = 0.f;
    for (int j = off + lane; j < end; j += 32) {
        float2 e = g_alpha0[j];
        float w0 = __expf(e.x - m0), w1 = __expf(e.y - m1);
        g_alpha0[j] = make_float2(w0, w1);
        d0 += w0; d1 += w1;
    }
#pragma unroll
    for (int o = 16; o; o >>= 1) {
        d0 += __shfl_xor_sync(0xffffffffu, d0, o);
        d1 += __shfl_xor_sync(0xffffffffu, d1, o);
    }
    float i0 = 1.f / (d0 + 1e-16f), i1 = 1.f / (d1 + 1e-16f);
    for (int j = off + lane; j < end; j += 32) {
        float2 a = g_alpha0[j];
        g_alpha0[j] = make_float2(a.x * i0, a.y * i1);
    }
}
__global__ void attn1_kernel() {
    int v = (blockIdx.x * blockDim.x + threadIdx.x) >> 5;
    int lane = threadIdx.x & 31;
    if (v >= NN) return;
    int off = g_offs[v], end = g_offs[v + 1];
    float sd = g_sd1[v];
    float m = -1e30f;
    for (int j = off + lane; j < end; j += 32) {
        int u = g_csr[j];
        float e = g_ss1[u] + sd;  e = e > 0.f ? e : 0.2f * e;
        g_alpha1[j] = e;
        m = fmaxf(m, e);
    }
#pragma unroll
    for (int o = 16; o; o >>= 1) m = fmaxf(m, __shfl_xor_sync(0xffffffffu, m, o));
    float d = 0.f;
    for (int j = off + lane; j < end; j += 32) {
        float w = __expf(g_alpha1[j] - m);
        g_alpha1[j] = w;
        d += w;
    }
#pragma unroll
    for (int o = 16; o; o >>= 1) d += __shfl_xor_sync(0xffffffffu, d, o);
    float iv = 1.f / (d + 1e-16f);
    for (int j = off + lane; j < end; j += 32) g_alpha1[j] *= iv;
}

// ============================================================================
// Aggregation (block per dst node, thread per channel; no atomics).
// Unroll deepened 4->8 for higher MLP (latency-bound gather loop).
// agg0 emits g directly as bf16 hi/lo (layer-1 GEMM A operand).
// ============================================================================
__global__ void __launch_bounds__(256) agg0_kernel(const float* __restrict__ b0) {
    int v = blockIdx.x;
    int tid = threadIdx.x;
    int head = tid >> 7;
    int off = g_offs[v], end = g_offs[v + 1];
    __shared__ int   su[32];
    __shared__ float sa[64];
    float acc = 0.f;
    for (int j0 = off; j0 < end; j0 += 32) {
        int cnt = min(32, end - j0);
        if (tid < cnt) su[tid] = g_csr[j0 + tid];
        if (tid >= 128 && tid < 128 + 2 * cnt)
            sa[tid - 128] = reinterpret_cast<const float*>(g_alpha0)[2 * j0 + (tid - 128)];
        __syncthreads();
        int j = 0;
        for (; j + 8 <= cnt; j += 8) {
            float x0 = __ldg(&g_h0[(size_t)su[j]     * HC0 + tid]);
            float x1 = __ldg(&g_h0[(size_t)su[j + 1] * HC0 + tid]);
            float x2 = __ldg(&g_h0[(size_t)su[j + 2] * HC0 + tid]);
            float x3 = __ldg(&g_h0[(size_t)su[j + 3] * HC0 + tid]);
            float x4 = __ldg(&g_h0[(size_t)su[j + 4] * HC0 + tid]);
            float x5 = __ldg(&g_h0[(size_t)su[j + 5] * HC0 + tid]);
            float x6 = __ldg(&g_h0[(size_t)su[j + 6] * HC0 + tid]);
            float x7 = __ldg(&g_h0[(size_t)su[j + 7] * HC0 + tid]);
            acc = fmaf(sa[2 * j + head],       x0, acc);
            acc = fmaf(sa[2 * (j + 1) + head], x1, acc);
            acc = fmaf(sa[2 * (j + 2) + head], x2, acc);
            acc = fmaf(sa[2 * (j + 3) + head], x3, acc);
            acc = fmaf(sa[2 * (j + 4) + head], x4, acc);
            acc = fmaf(sa[2 * (j + 5) + head], x5, acc);
            acc = fmaf(sa[2 * (j + 6) + head], x6, acc);
            acc = fmaf(sa[2 * (j + 7) + head], x7, acc);
        }
        for (; j + 4 <= cnt; j += 4) {
            float x0 = __ldg(&g_h0[(size_t)su[j]     * HC0 + tid]);
            float x1 = __ldg(&g_h0[(size_t)su[j + 1] * HC0 + tid]);
            float x2 = __ldg(&g_h0[(size_t)su[j + 2] * HC0 + tid]);
            float x3 = __ldg(&g_h0[(size_t)su[j + 3] * HC0 + tid]);
            acc = fmaf(sa[2 * j + head],       x0, acc);
            acc = fmaf(sa[2 * (j + 1) + head], x1, acc);
            acc = fmaf(sa[2 * (j + 2) + head], x2, acc);
            acc = fmaf(sa[2 * (j + 3) + head], x3, acc);
        }
        for (; j < cnt; j++)
            acc = fmaf(sa[2 * j + head], __ldg(&g_h0[(size_t)su[j] * HC0 + tid]), acc);
        __syncthreads();
    }
    float val = acc + b0[tid];
    val = val > 0.f ? val : expm1f(val);   // elu
    __nv_bfloat16 h = __float2bfloat16(val);
    size_t oidx = (size_t)v * HC0 + tid;
    g_ghi[oidx] = h;
    g_glo[oidx] = __float2bfloat16(val - __bfloat162float(h));
}

__global__ void __launch_bounds__(128)
agg1_kernel(const float* __restrict__ x, const float* __restrict__ b1,
            float* __restrict__ out) {
    int v = blockIdx.x;
    int tid = threadIdx.x;
    int off = g_offs[v], end = g_offs[v + 1];
    __shared__ int   su[32];
    __shared__ float sa[32];
    float acc = 0.f;
    for (int j0 = off; j0 < end; j0 += 32) {
        int cnt = min(32, end - j0);
        if (tid < cnt) su[tid] = g_csr[j0 + tid];
        if (tid >= 64 && tid < 64 + cnt) sa[tid - 64] = g_alpha1[j0 + (tid - 64)];
        __syncthreads();
        int j = 0;
        for (; j + 8 <= cnt; j += 8) {
            float x0 = __ldg(&g_h1[(size_t)su[j]     * C1 + tid]);
            float x1 = __ldg(&g_h1[(size_t)su[j + 1] * C1 + tid]);
            float x2 = __ldg(&g_h1[(size_t)su[j + 2] * C1 + tid]);
            float x3 = __ldg(&g_h1[(size_t)su[j + 3] * C1 + tid]);
            float x4 = __ldg(&g_h1[(size_t)su[j + 4] * C1 + tid]);
            float x5 = __ldg(&g_h1[(size_t)su[j + 5] * C1 + tid]);
            float x6 = __ldg(&g_h1[(size_t)su[j + 6] * C1 + tid]);
            float x7 = __ldg(&g_h1[(size_t)su[j + 7] * C1 + tid]);
            acc = fmaf(sa[j],     x0, acc);
            acc = fmaf(sa[j + 1], x1, acc);
            acc = fmaf(sa[j + 2], x2, acc);
            acc = fmaf(sa[j + 3], x3, acc);
            acc = fmaf(sa[j + 4], x4, acc);
            acc = fmaf(sa[j + 5], x5, acc);
            acc = fmaf(sa[j + 6], x6, acc);
            acc = fmaf(sa[j + 7], x7, acc);
        }
        for (; j + 4 <= cnt; j += 4) {
            float x0 = __ldg(&g_h1[(size_t)su[j]     * C1 + tid]);
            float x1 = __ldg(&g_h1[(size_t)su[j + 1] * C1 + tid]);
            float x2 = __ldg(&g_h1[(size_t)su[j + 2] * C1 + tid]);
            float x3 = __ldg(&g_h1[(size_t)su[j + 3] * C1 + tid]);
            acc = fmaf(sa[j],     x0, acc);
            acc = fmaf(sa[j + 1], x1, acc);
            acc = fmaf(sa[j + 2], x2, acc);
            acc = fmaf(sa[j + 3], x3, acc);
        }
        for (; j < cnt; j++)
            acc = fmaf(sa[j], __ldg(&g_h1[(size_t)su[j] * C1 + tid]), acc);
        __syncthreads();
    }
    out[(size_t)v * C1 + tid] = x[(size_t)v * C1 + tid] + acc + b1[tid];
}

// ============================================================================
// Launch (exact R7 order)
// ============================================================================
extern "C" void kernel_launch(void* const* d_in, const int* in_sizes, int n_in,
                              void* d_out, int out_size) {
    const float* x      = (const float*)d_in[0];
    const float* W0     = (const float*)d_in[1];
    const float* a_src0 = (const float*)d_in[2];
    const float* a_dst0 = (const float*)d_in[3];
    const float* b0     = (const float*)d_in[4];
    const float* W1     = (const float*)d_in[5];
    const float* a_src1 = (const float*)d_in[6];
    const float* a_dst1 = (const float*)d_in[7];
    const float* b1     = (const float*)d_in[8];
    const int*   eidx   = (const int*)d_in[9];
    float* out = (float*)d_out;

    int E = in_sizes[9] / 2;
    if (E > EMAX) E = EMAX;
    const int* esrc = eidx;
    const int* edst = eidx + E;

    float *h0p = nullptr, *h1p = nullptr;
    __nv_bfloat16 *xhi, *xlo, *ghi, *glo, *w0thi, *w0tlo, *w1thi, *w1tlo;
    cudaGetSymbolAddress((void**)&h0p,   g_h0);
    cudaGetSymbolAddress((void**)&h1p,   g_h1);
    cudaGetSymbolAddress((void**)&xhi,   g_xhi);
    cudaGetSymbolAddress((void**)&xlo,   g_xlo);
    cudaGetSymbolAddress((void**)&ghi,   g_ghi);
    cudaGetSymbolAddress((void**)&glo,   g_glo);
    cudaGetSymbolAddress((void**)&w0thi, g_w0thi);
    cudaGetSymbolAddress((void**)&w0tlo, g_w0tlo);
    cudaGetSymbolAddress((void**)&w1thi, g_w1thi);
    cudaGetSymbolAddress((void**)&w1tlo, g_w1tlo);

    const int T = 256;
    int nWarpBlocks = (NN * 32 + T - 1) / T;
    int mTiles = (NN + 127) / 128;   // 391

    // conversions + CSR build
    split_x_kernel<<<(NN * 128 + T - 1) / T, T>>>(x);
    splitT_kernel<<<(128 * 256 + T - 1) / T, T>>>(W0, w0thi, w0tlo, 128, 256);
    splitT_kernel<<<(256 * 128 + T - 1) / T, T>>>(W1, w1thi, w1tlo, 256, 128);
    init_deg_kernel<<<(NN + T - 1) / T, T>>>();
    count_kernel<<<(E + T - 1) / T, T>>>(edst, E);
    scan_kernel<<<1, 1024>>>();
    scatter_kernel<<<(E + NN + T - 1) / T, T>>>(esrc, edst, E);

    // Layer 0
    gemm_bf16_kernel<<<dim3(mTiles, 2), 256>>>(xhi, xlo, w0thi, w0tlo,
                                               h0p, 128, HC0);
    sfuse0_kernel<<<nWarpBlocks, T>>>(a_src0, a_dst0);
    attn0_kernel<<<nWarpBlocks, T>>>();
    agg0_kernel<<<NN, 256>>>(b0);

    // Layer 1
    gemm_bf16_kernel<<<dim3(mTiles, 1), 256>>>(ghi, glo, w1thi, w1tlo,
                                               h1p, 256, C1);
    sfuse1_kernel<<<nWarpBlocks, T>>>(a_src1, a_dst1);
    attn1_kernel<<<nWarpBlocks, T>>>();
    agg1_kernel<<<NN, 128>>>(x, b1, out);
}